// round 12
// baseline (speedup 1.0000x reference)
#include <cuda_runtime.h>
#include <cuda_fp16.h>
#include <cstdint>
#include <cstddef>

#define NL 5
#define H 1024
#define T_STEPS 128
#define BS 512
#define G4 4096
#define NCTA 128
#define LBH ((size_t)NL * BS * H)

#define ROWB 272              // bytes per smem row: 256B (128 halfs) + 16B pad
#define ATILE (128 * ROWB)    // 34816 B
#define STAGE (2 * ATILE)     // 69632 B (A + B)
#define OFFB ATILE
#define GS 132                // gate-smem row stride in words
#define SMEM_REQ (3 * STAGE)  // 208896 B

// Device-global scratch (no allocations allowed)
__device__ __half g_h[2 * NL * BS * H];    // h ping-pong by step parity (fp16)
__device__ float  g_c[NL * BS * H];        // full fp32 cell state
__device__ float  g_x0[BS];
__device__ unsigned g_bar;
__device__ __half g_Wih[(NL - 1) * G4 * H]; // fp16 W_ih (layers 1..4)
__device__ __half g_Whh[NL * G4 * H];       // fp16 W_hh

__device__ __forceinline__ uint32_t smem_u32(const void* p) {
    uint32_t a;
    asm("{ .reg .u64 t; cvta.to.shared.u64 t, %1; cvt.u32.u64 %0, t; }" : "=r"(a) : "l"(p));
    return a;
}
__device__ __forceinline__ void cp16(uint32_t dst, const void* src) {
    asm volatile("cp.async.cg.shared.global [%0], [%1], 16;" :: "r"(dst), "l"(src));
}
__device__ __forceinline__ void cp_commit() { asm volatile("cp.async.commit_group;" ::: "memory"); }
__device__ __forceinline__ void cp_wait1() { asm volatile("cp.async.wait_group 1;" ::: "memory"); }
__device__ __forceinline__ void ldsm4(uint32_t& r0, uint32_t& r1, uint32_t& r2, uint32_t& r3,
                                      uint32_t addr) {
    asm volatile("ldmatrix.sync.aligned.m8n8.x4.shared.b16 {%0,%1,%2,%3}, [%4];"
        : "=r"(r0), "=r"(r1), "=r"(r2), "=r"(r3) : "r"(addr));
}
// m16n8k16 fp16 inputs, fp32 accumulate
__device__ __forceinline__ void mma16(float* c, const uint32_t* a, const uint32_t* b) {
    asm volatile(
        "mma.sync.aligned.m16n8k16.row.col.f32.f16.f16.f32 "
        "{%0,%1,%2,%3}, {%4,%5,%6,%7}, {%8,%9}, {%0,%1,%2,%3};\n"
        : "+f"(c[0]), "+f"(c[1]), "+f"(c[2]), "+f"(c[3])
        : "r"(a[0]), "r"(a[1]), "r"(a[2]), "r"(a[3]),
          "r"(b[0]), "r"(b[1]));
}
__device__ __forceinline__ float sigf(float x) { return 1.f / (1.f + __expf(-x)); }

__device__ __forceinline__ void grid_sync(unsigned& gen) {
    __syncthreads();
    if (threadIdx.x == 0) {
        __threadfence();
        atomicAdd(&g_bar, 1u);
        const unsigned target = gen * NCTA + NCTA;
        while (*(volatile unsigned*)&g_bar < target) {}
        __threadfence();
    }
    gen++;
    __syncthreads();
}

__global__ void lstm_init(const float* __restrict__ x) {
    const int idx = blockIdx.x * blockDim.x + threadIdx.x;
    if (idx < NL * BS * H) {
        const float v = x[idx & (BS * H - 1)];
        g_h[LBH + idx] = __float2half_rn(v);  // parity-1 buffer (read at t=0)
        g_c[idx] = v;                          // exact fp32
    }
    if (idx < BS) g_x0[idx] = 0.f;
    if (idx == 0) g_bar = 0u;
}

__global__ __launch_bounds__(256, 1)
void lstm_persist(const float* __restrict__ Wihr_f, const float* __restrict__ Whh_f,
                  const float* __restrict__ Wih0, const float* __restrict__ bih,
                  const float* __restrict__ bhh,  const float* __restrict__ Wro,
                  const float* __restrict__ bro,  float* __restrict__ y)
{
    extern __shared__ float dynf[];
    __shared__ float rsm[8];

    const uint32_t sbase = smem_u32(dynf);

    const int tid  = threadIdx.x;
    const int lane = tid & 31;
    const int wid  = tid >> 5;
    const int gid  = lane >> 2;
    const int tl   = lane & 3;
    const int l7   = lane & 7;
    const int quad = lane >> 3;
    const int wm   = wid & 1;         // 64-row slab
    const int wn   = (wid >> 1) & 1;  // 64-col slab
    const int wk   = wid >> 2;        // k-split half (4 k16-groups each)

    const int ct = blockIdx.x;
    const int m0 = (ct >> 5) * 128;   // batch tile
    const int jn = (ct & 31) * 32;    // 32-wide n-group within each gate

    unsigned gen = 0;

    // ---- prologue: fp32 -> fp16 weight conversion (replaces wconv kernel) ----
    {
        const int n1 = (NL - 1) * G4 * H / 4;
        const int n2 = NL * G4 * H / 4;
        const float4* shh = (const float4*)Whh_f;
        const float4* sih = (const float4*)Wihr_f;
        __half2* dhh = (__half2*)g_Whh;
        __half2* dih = (__half2*)g_Wih;
        for (int i = ct * 256 + tid; i < n2; i += NCTA * 256) {
            const float4 v = shh[i];
            dhh[2 * i]     = __floats2half2_rn(v.x, v.y);
            dhh[2 * i + 1] = __floats2half2_rn(v.z, v.w);
            if (i < n1) {
                const float4 u = sih[i];
                dih[2 * i]     = __floats2half2_rn(u.x, u.y);
                dih[2 * i + 1] = __floats2half2_rn(u.z, u.w);
            }
        }
    }
    grid_sync(gen);

    // ---- flat chunk stream: fill cursor runs 2 chunks ahead, across barriers ----
    // Layer chunk order: ch 0..7 = W_hh x h_old (always ready), ch 8..15 = W_ih x h_new.
    int ft = 0, fl = 0, fc = 0, fslot = 0;
    auto do_fill = [&]() {
        const int fp = ft & 1;
        const __half* A; const __half* W; int k0;
        if (fc < 8) {
            A = g_h + (size_t)(fp ^ 1) * LBH + (size_t)fl * BS * H;
            W = g_Whh + (size_t)fl * G4 * H;
            k0 = fc * 128;
        } else {
            A = g_h + (size_t)fp * LBH + (size_t)(fl - 1) * BS * H;
            W = g_Wih + (size_t)(fl - 1) * G4 * H;
            k0 = (fc - 8) * 128;
        }
        const uint32_t sa = sbase + fslot * STAGE;
        const uint32_t sb = sa + OFFB;
        #pragma unroll
        for (int i = 0; i < 8; ++i) {
            const int idx = tid + i * 256;     // 2048 (row, 16B-seg) pairs
            const int row = idx >> 4;
            const int seg = idx & 15;
            cp16(sa + row * ROWB + seg * 16, A + (size_t)(m0 + row) * H + k0 + seg * 8);
            const int wrow = ((row >> 5) << 10) + jn + (row & 31);
            cp16(sb + row * ROWB + seg * 16, W + (size_t)wrow * H + k0 + seg * 8);
        }
        cp_commit();
        fslot = (fslot == 2) ? 0 : fslot + 1;
        const int ncf = (fl == 0) ? 8 : 16;
        if (++fc == ncf) { fc = 0; if (++fl == NL) { fl = 0; ++ft; } }
    };

    do_fill(); do_fill();   // prime: stream chunks 0,1
    int cslot = 0;

    #pragma unroll 1
    for (int t = 0; t < T_STEPS; ++t) {
        const int p = t & 1;
        #pragma unroll 1
        for (int l = 0; l < NL; ++l) {
            const int nc = (l == 0) ? 8 : 16;

            float acc[4][8][4];
            #pragma unroll
            for (int a = 0; a < 4; ++a)
                #pragma unroll
                for (int b = 0; b < 8; ++b)
                    #pragma unroll
                    for (int r = 0; r < 4; ++r) acc[a][b][r] = 0.f;

            #pragma unroll 1
            for (int ch = 0; ch < nc; ++ch) {
                cp_wait1();           // own groups: current chunk complete
                __syncthreads();      // everyone's writes visible; prev compute done
                do_fill();            // fill chunk (stream+2) into the just-freed slot
                {   // compute current chunk from slot cslot
                    const uint32_t sa = sbase + cslot * STAGE;
                    const uint32_t sb = sa + OFFB;
                    #pragma unroll
                    for (int ks = 0; ks < 4; ++ks) {
                        const int ksg = wk * 4 + ks;       // k16-group 0..7
                        const uint32_t koff = ksg * 32;    // bytes
                        uint32_t af[4][4], bf[8][2];
                        #pragma unroll
                        for (int mt = 0; mt < 4; ++mt) {
                            const int arow = wm * 64 + mt * 16 + (quad & 1) * 8 + l7;
                            const uint32_t ao = sa + arow * ROWB + koff + (quad >> 1) * 16;
                            ldsm4(af[mt][0], af[mt][1], af[mt][2], af[mt][3], ao);
                        }
                        #pragma unroll
                        for (int q = 0; q < 4; ++q) {
                            const int nrow = wn * 64 + q * 16 + (quad >> 1) * 8 + l7;
                            const uint32_t bo = sb + nrow * ROWB + koff + (quad & 1) * 16;
                            ldsm4(bf[2 * q][0], bf[2 * q][1], bf[2 * q + 1][0], bf[2 * q + 1][1], bo);
                        }
                        #pragma unroll
                        for (int mt = 0; mt < 4; ++mt)
                            #pragma unroll
                            for (int nt = 0; nt < 8; ++nt)
                                mma16(acc[mt][nt], af[mt], bf[nt]);
                    }
                }
                cslot = (cslot == 2) ? 0 : cslot + 1;
            }
            __syncthreads();          // all frag reads done before gsm overlays last slot

            // gate buffer overlays the slot of this layer's LAST computed chunk
            float* gsm = dynf + ((cslot + 2) % 3) * (STAGE / 4);

            // ---- k-split reduction through smem ----
            if (wk == 1) {
                #pragma unroll
                for (int mt = 0; mt < 4; ++mt) {
                    const int r = wm * 64 + mt * 16 + gid;
                    #pragma unroll
                    for (int nt = 0; nt < 8; ++nt) {
                        const int c = wn * 64 + nt * 8 + 2 * tl;
                        *(float2*)&gsm[r * GS + c]       = make_float2(acc[mt][nt][0], acc[mt][nt][1]);
                        *(float2*)&gsm[(r + 8) * GS + c] = make_float2(acc[mt][nt][2], acc[mt][nt][3]);
                    }
                }
            }
            __syncthreads();
            if (wk == 0) {
                #pragma unroll
                for (int mt = 0; mt < 4; ++mt) {
                    const int r = wm * 64 + mt * 16 + gid;
                    #pragma unroll
                    for (int nt = 0; nt < 8; ++nt) {
                        const int c = wn * 64 + nt * 8 + 2 * tl;
                        float2 p0 = *(float2*)&gsm[r * GS + c];
                        float2 p1 = *(float2*)&gsm[(r + 8) * GS + c];
                        *(float2*)&gsm[r * GS + c] =
                            make_float2(p0.x + acc[mt][nt][0], p0.y + acc[mt][nt][1]);
                        *(float2*)&gsm[(r + 8) * GS + c] =
                            make_float2(p1.x + acc[mt][nt][2], p1.y + acc[mt][nt][3]);
                    }
                }
            }
            __syncthreads();

            // ---- fused LSTM pointwise from smem gates ----
            {
                const float* bi = bih + l * G4;
                const float* bh = bhh + l * G4;
                #pragma unroll
                for (int it = 0; it < 4; ++it) {
                    const int g   = tid + it * 256;
                    const int b   = g >> 3;          // local batch row 0..127
                    const int nn4 = (g & 7) * 4;     // n offset 0..28
                    const float4 vi = *(const float4*)&gsm[b * GS + nn4];
                    const float4 vf = *(const float4*)&gsm[b * GS + 32 + nn4];
                    const float4 vg = *(const float4*)&gsm[b * GS + 64 + nn4];
                    const float4 vo = *(const float4*)&gsm[b * GS + 96 + nn4];
                    const int brow = m0 + b;
                    const int n0 = jn + nn4;
                    float xv = 0.f;
                    if (l == 0) xv = g_x0[brow];
                    float*  cp = g_c + (size_t)l * BS * H + (size_t)brow * H + n0;
                    __half* hp = g_h + (size_t)p * LBH + (size_t)l * BS * H + (size_t)brow * H + n0;
                    const float4 cold = *(const float4*)cp;
                    float hv[4], cv[4];
                    const float* vip = (const float*)&vi;
                    const float* vfp = (const float*)&vf;
                    const float* vgp = (const float*)&vg;
                    const float* vop = (const float*)&vo;
                    const float* cop = (const float*)&cold;
                    #pragma unroll
                    for (int q = 0; q < 4; ++q) {
                        const int n = n0 + q;
                        float pi = vip[q] + bi[n]         + bh[n];
                        float pf = vfp[q] + bi[H + n]     + bh[H + n];
                        float pg = vgp[q] + bi[2 * H + n] + bh[2 * H + n];
                        float po = vop[q] + bi[3 * H + n] + bh[3 * H + n];
                        if (l == 0) {
                            pi += xv * Wih0[n];
                            pf += xv * Wih0[H + n];
                            pg += xv * Wih0[2 * H + n];
                            po += xv * Wih0[3 * H + n];
                        }
                        const float cn = sigf(pf) * cop[q] + sigf(pi) * tanhf(pg);
                        cv[q] = cn;
                        hv[q] = sigf(po) * tanhf(cn);
                    }
                    *(float4*)cp = make_float4(cv[0], cv[1], cv[2], cv[3]);
                    __half2* hp2 = reinterpret_cast<__half2*>(hp);
                    hp2[0] = __floats2half2_rn(hv[0], hv[1]);
                    hp2[1] = __floats2half2_rn(hv[2], hv[3]);
                }
            }
            grid_sync(gen);
        }

        // ---- readout: 4 batch rows per CTA, 2 warps per row ----
        {
            const int row  = ct * 4 + (wid >> 1);
            const int half = wid & 1;
            const __half2* hr = reinterpret_cast<const __half2*>(
                g_h + (size_t)p * LBH + (size_t)(NL - 1) * BS * H
                + (size_t)row * H + half * 512);
            const float* wr = Wro + half * 512;
            float s = 0.f;
            #pragma unroll
            for (int i = 0; i < 8; ++i) {
                const int k2 = lane + i * 32;        // half2 index 0..255
                const float2 hv = __half22float2(hr[k2]);
                s += hv.x * wr[2 * k2] + hv.y * wr[2 * k2 + 1];
            }
            #pragma unroll
            for (int o = 16; o; o >>= 1) s += __shfl_xor_sync(0xffffffffu, s, o);
            if (lane == 0) rsm[wid] = s;
            __syncthreads();
            if (tid < 4) {
                const float v = rsm[2 * tid] + rsm[2 * tid + 1] + bro[0];
                const int b = ct * 4 + tid;
                y[(size_t)b * T_STEPS + t] = v;
                g_x0[b] = v;
            }
            grid_sync(gen);
        }
    }
}

extern "C" void kernel_launch(void* const* d_in, const int* in_sizes, int n_in,
                              void* d_out, int out_size)
{
    const float* x     = (const float*)d_in[0];  // (512, 1024)
    const float* W_ih0 = (const float*)d_in[1];  // (4096, 1)
    const float* W_ihr = (const float*)d_in[2];  // (4, 4096, 1024)
    const float* W_hh  = (const float*)d_in[3];  // (5, 4096, 1024)
    const float* b_ih  = (const float*)d_in[4];  // (5, 4096)
    const float* b_hh  = (const float*)d_in[5];  // (5, 4096)
    const float* W_ro  = (const float*)d_in[6];  // (1, 1024)
    const float* b_ro  = (const float*)d_in[7];  // (1,)
    float* y = (float*)d_out;                    // (512, 128, 1)

    cudaFuncSetAttribute(lstm_persist, cudaFuncAttributeMaxDynamicSharedMemorySize, SMEM_REQ);

    lstm_init<<<(NL * BS * H + 255) / 256, 256>>>(x);
    lstm_persist<<<NCTA, 256, SMEM_REQ>>>(W_ihr, W_hh, W_ih0, b_ih, b_hh, W_ro, b_ro, y);
}

// round 13
// speedup vs baseline: 1.5539x; 1.5539x over previous
#include <cuda_runtime.h>
#include <cuda_fp16.h>
#include <cstdint>
#include <cstddef>

#define NL 5
#define H 1024
#define T_STEPS 128
#define BS 512
#define G4 4096
#define NCTA 128
#define NT 512
#define LBH ((size_t)NL * BS * H)

#define ROWB 272              // bytes per smem row: 256B (128 halfs) + 16B pad
#define ATILE (128 * ROWB)    // 34816 B
#define STAGE (2 * ATILE)     // 69632 B (A + B)
#define OFFB ATILE
#define GS 132                // gate-smem row stride in words
#define SMEM_REQ (3 * STAGE)  // 208896 B

// Device-global scratch (no allocations allowed)
__device__ __half g_h[2 * NL * BS * H];    // h ping-pong by step parity (fp16)
__device__ float  g_c[NL * BS * H];        // full fp32 cell state
__device__ float  g_x0[BS];
__device__ unsigned g_bar;
__device__ __half g_Wih[(NL - 1) * G4 * H]; // fp16 W_ih (layers 1..4)
__device__ __half g_Whh[NL * G4 * H];       // fp16 W_hh

__device__ __forceinline__ uint32_t smem_u32(const void* p) {
    uint32_t a;
    asm("{ .reg .u64 t; cvta.to.shared.u64 t, %1; cvt.u32.u64 %0, t; }" : "=r"(a) : "l"(p));
    return a;
}
__device__ __forceinline__ void cp16(uint32_t dst, const void* src) {
    asm volatile("cp.async.cg.shared.global [%0], [%1], 16;" :: "r"(dst), "l"(src));
}
__device__ __forceinline__ void cp_commit() { asm volatile("cp.async.commit_group;" ::: "memory"); }
__device__ __forceinline__ void cp_wait(int allow) {
    if (allow <= 0)      asm volatile("cp.async.wait_group 0;" ::: "memory");
    else                 asm volatile("cp.async.wait_group 1;" ::: "memory");
}
__device__ __forceinline__ void ldsm4(uint32_t& r0, uint32_t& r1, uint32_t& r2, uint32_t& r3,
                                      uint32_t addr) {
    asm volatile("ldmatrix.sync.aligned.m8n8.x4.shared.b16 {%0,%1,%2,%3}, [%4];"
        : "=r"(r0), "=r"(r1), "=r"(r2), "=r"(r3) : "r"(addr));
}
// m16n8k16 fp16 inputs, fp32 accumulate
__device__ __forceinline__ void mma16(float* c, const uint32_t* a, const uint32_t* b) {
    asm volatile(
        "mma.sync.aligned.m16n8k16.row.col.f32.f16.f16.f32 "
        "{%0,%1,%2,%3}, {%4,%5,%6,%7}, {%8,%9}, {%0,%1,%2,%3};\n"
        : "+f"(c[0]), "+f"(c[1]), "+f"(c[2]), "+f"(c[3])
        : "r"(a[0]), "r"(a[1]), "r"(a[2]), "r"(a[3]),
          "r"(b[0]), "r"(b[1]));
}
__device__ __forceinline__ float sigf(float x) { return 1.f / (1.f + __expf(-x)); }

__device__ __forceinline__ void grid_sync(unsigned& gen) {
    __syncthreads();
    if (threadIdx.x == 0) {
        __threadfence();
        atomicAdd(&g_bar, 1u);
        const unsigned target = gen * NCTA + NCTA;
        while (*(volatile unsigned*)&g_bar < target) {}
        __threadfence();
    }
    gen++;
    __syncthreads();
}

__global__ void wconv(const float* __restrict__ Wihr, const float* __restrict__ Whh) {
    const int n1 = (NL - 1) * G4 * H, n2 = NL * G4 * H;
    for (int i = blockIdx.x * blockDim.x + threadIdx.x; i < n2; i += gridDim.x * blockDim.x) {
        if (i < n1) g_Wih[i] = __float2half_rn(Wihr[i]);
        g_Whh[i] = __float2half_rn(Whh[i]);
    }
}

__global__ void lstm_init(const float* __restrict__ x) {
    const int idx = blockIdx.x * blockDim.x + threadIdx.x;
    if (idx < NL * BS * H) {
        const float v = x[idx & (BS * H - 1)];
        g_h[LBH + idx] = __float2half_rn(v);  // parity-1 buffer (read at t=0)
        g_c[idx] = v;                          // exact fp32
    }
    if (idx < BS) g_x0[idx] = 0.f;
    if (idx == 0) g_bar = 0u;
}

__global__ __launch_bounds__(NT, 1)
void lstm_persist(const float* __restrict__ Wih0, const float* __restrict__ bih,
                  const float* __restrict__ bhh,  const float* __restrict__ Wro,
                  const float* __restrict__ bro,  float* __restrict__ y)
{
    extern __shared__ float dynf[];
    __shared__ float rsm[16];

    const uint32_t sbase = smem_u32(dynf);
    float* gsm = dynf;   // 128 x GS gate buffer (overlays ring when idle)

    const int tid  = threadIdx.x;
    const int lane = tid & 31;
    const int wid  = tid >> 5;        // 0..15
    const int gid  = lane >> 2;
    const int tl   = lane & 3;
    const int l7   = lane & 7;
    const int quad = lane >> 3;
    const int wm   = wid & 3;         // 32-row slab (0..3)
    const int wn   = (wid >> 2) & 1;  // 64-col slab
    const int wk   = wid >> 3;        // k-split half (4 k16-groups each)

    const int ct = blockIdx.x;
    const int m0 = (ct >> 5) * 128;   // batch tile
    const int jn = (ct & 31) * 32;    // 32-wide n-group within each gate

    unsigned gen = 0;

    #pragma unroll 1
    for (int t = 0; t < T_STEPS; ++t) {
        const int p = t & 1;
        #pragma unroll 1
        for (int l = 0; l < NL; ++l) {
            const __half* A1 = (l == 0) ? nullptr : g_h + (size_t)p * LBH + (size_t)(l - 1) * BS * H;
            const __half* W1 = (l == 0) ? nullptr : g_Wih + (size_t)(l - 1) * G4 * H;
            const __half* A2 = g_h + (size_t)(p ^ 1) * LBH + (size_t)l * BS * H;
            const __half* W2 = g_Whh + (size_t)l * G4 * H;
            const int c1 = (l == 0) ? 0 : 8;    // chunks of K=128 halfs
            const int nc = c1 + 8;

            float acc[2][8][4];
            #pragma unroll
            for (int a = 0; a < 2; ++a)
                #pragma unroll
                for (int b = 0; b < 8; ++b)
                    #pragma unroll
                    for (int r = 0; r < 4; ++r) acc[a][b][r] = 0.f;

            auto fill = [&](int ch) {
                const int slot = ch % 3;
                const __half* A; const __half* W; int k0;
                if (ch < c1) { A = A1; W = W1; k0 = ch * 128; }
                else         { A = A2; W = W2; k0 = (ch - c1) * 128; }
                const uint32_t sa = sbase + slot * STAGE;
                const uint32_t sb = sa + OFFB;
                #pragma unroll
                for (int i = 0; i < 4; ++i) {
                    const int idx = tid + i * NT;      // 2048 (row, 16B-seg) pairs
                    const int row = idx >> 4;
                    const int seg = idx & 15;          // 8 halfs per 16B
                    cp16(sa + row * ROWB + seg * 16, A + (size_t)(m0 + row) * H + k0 + seg * 8);
                    const int wrow = ((row >> 5) << 10) + jn + (row & 31);
                    cp16(sb + row * ROWB + seg * 16, W + (size_t)wrow * H + k0 + seg * 8);
                }
                cp_commit();
            };

            auto compute = [&](int ch) {
                const int slot = ch % 3;
                const uint32_t sa = sbase + slot * STAGE;
                const uint32_t sb = sa + OFFB;
                #pragma unroll
                for (int ks = 0; ks < 4; ++ks) {
                    const int ksg = wk * 4 + ks;       // k16-group 0..7
                    const uint32_t koff = ksg * 32;    // bytes
                    uint32_t af[2][4], bf[8][2];
                    #pragma unroll
                    for (int mt = 0; mt < 2; ++mt) {
                        const int arow = wm * 32 + mt * 16 + (quad & 1) * 8 + l7;
                        const uint32_t ao = sa + arow * ROWB + koff + (quad >> 1) * 16;
                        ldsm4(af[mt][0], af[mt][1], af[mt][2], af[mt][3], ao);
                    }
                    #pragma unroll
                    for (int q = 0; q < 4; ++q) {
                        const int nrow = wn * 64 + q * 16 + (quad >> 1) * 8 + l7;
                        const uint32_t bo = sb + nrow * ROWB + koff + (quad & 1) * 16;
                        ldsm4(bf[2 * q][0], bf[2 * q][1], bf[2 * q + 1][0], bf[2 * q + 1][1], bo);
                    }
                    #pragma unroll
                    for (int mt = 0; mt < 2; ++mt)
                        #pragma unroll
                        for (int nt = 0; nt < 8; ++nt)
                            mma16(acc[mt][nt], af[mt], bf[nt]);
                }
            };

            fill(0); fill(1);
            #pragma unroll 1
            for (int ch = 0; ch < nc; ++ch) {
                const int committed = (ch + 2 < nc) ? (ch + 2) : nc;
                cp_wait(committed - ch - 1);   // own groups through ch complete
                __syncthreads();               // everyone's writes for ch visible
                if (ch + 2 < nc) fill(ch + 2);
                compute(ch);
            }
            __syncthreads();                   // all frag reads done before gsm overlays ring

            // ---- k-split reduction through smem ----
            if (wk == 1) {
                #pragma unroll
                for (int mt = 0; mt < 2; ++mt) {
                    const int r = wm * 32 + mt * 16 + gid;
                    #pragma unroll
                    for (int nt = 0; nt < 8; ++nt) {
                        const int c = wn * 64 + nt * 8 + 2 * tl;
                        *(float2*)&gsm[r * GS + c]       = make_float2(acc[mt][nt][0], acc[mt][nt][1]);
                        *(float2*)&gsm[(r + 8) * GS + c] = make_float2(acc[mt][nt][2], acc[mt][nt][3]);
                    }
                }
            }
            __syncthreads();
            if (wk == 0) {
                #pragma unroll
                for (int mt = 0; mt < 2; ++mt) {
                    const int r = wm * 32 + mt * 16 + gid;
                    #pragma unroll
                    for (int nt = 0; nt < 8; ++nt) {
                        const int c = wn * 64 + nt * 8 + 2 * tl;
                        float2 p0 = *(float2*)&gsm[r * GS + c];
                        float2 p1 = *(float2*)&gsm[(r + 8) * GS + c];
                        *(float2*)&gsm[r * GS + c] =
                            make_float2(p0.x + acc[mt][nt][0], p0.y + acc[mt][nt][1]);
                        *(float2*)&gsm[(r + 8) * GS + c] =
                            make_float2(p1.x + acc[mt][nt][2], p1.y + acc[mt][nt][3]);
                    }
                }
            }
            __syncthreads();

            // ---- fused LSTM pointwise from smem gates ----
            {
                const float* bi = bih + l * G4;
                const float* bh = bhh + l * G4;
                #pragma unroll
                for (int it = 0; it < 2; ++it) {
                    const int g   = tid + it * NT;
                    const int b   = g >> 3;          // local batch row 0..127
                    const int nn4 = (g & 7) * 4;     // n offset 0..28
                    const float4 vi = *(const float4*)&gsm[b * GS + nn4];
                    const float4 vf = *(const float4*)&gsm[b * GS + 32 + nn4];
                    const float4 vg = *(const float4*)&gsm[b * GS + 64 + nn4];
                    const float4 vo = *(const float4*)&gsm[b * GS + 96 + nn4];
                    const int brow = m0 + b;
                    const int n0 = jn + nn4;
                    float xv = 0.f;
                    if (l == 0) xv = g_x0[brow];
                    float*  cp = g_c + (size_t)l * BS * H + (size_t)brow * H + n0;
                    __half* hp = g_h + (size_t)p * LBH + (size_t)l * BS * H + (size_t)brow * H + n0;
                    const float4 cold = *(const float4*)cp;
                    float hv[4], cv[4];
                    const float* vip = (const float*)&vi;
                    const float* vfp = (const float*)&vf;
                    const float* vgp = (const float*)&vg;
                    const float* vop = (const float*)&vo;
                    const float* cop = (const float*)&cold;
                    #pragma unroll
                    for (int q = 0; q < 4; ++q) {
                        const int n = n0 + q;
                        float pi = vip[q] + bi[n]         + bh[n];
                        float pf = vfp[q] + bi[H + n]     + bh[H + n];
                        float pg = vgp[q] + bi[2 * H + n] + bh[2 * H + n];
                        float po = vop[q] + bi[3 * H + n] + bh[3 * H + n];
                        if (l == 0) {
                            pi += xv * Wih0[n];
                            pf += xv * Wih0[H + n];
                            pg += xv * Wih0[2 * H + n];
                            po += xv * Wih0[3 * H + n];
                        }
                        const float cn = sigf(pf) * cop[q] + sigf(pi) * tanhf(pg);
                        cv[q] = cn;
                        hv[q] = sigf(po) * tanhf(cn);
                    }
                    *(float4*)cp = make_float4(cv[0], cv[1], cv[2], cv[3]);
                    __half2* hp2 = reinterpret_cast<__half2*>(hp);
                    hp2[0] = __floats2half2_rn(hv[0], hv[1]);
                    hp2[1] = __floats2half2_rn(hv[2], hv[3]);
                }
            }
            grid_sync(gen);
        }

        // ---- readout: 4 batch rows per CTA, 4 warps per row ----
        {
            const int row = ct * 4 + (wid >> 2);
            const int qtr = wid & 3;
            const __half2* hr = reinterpret_cast<const __half2*>(
                g_h + (size_t)p * LBH + (size_t)(NL - 1) * BS * H
                + (size_t)row * H + qtr * 256);
            const float* wr = Wro + qtr * 256;
            float s = 0.f;
            #pragma unroll
            for (int i = 0; i < 4; ++i) {
                const int k2 = lane + i * 32;        // half2 index 0..127
                const float2 hv = __half22float2(hr[k2]);
                s += hv.x * wr[2 * k2] + hv.y * wr[2 * k2 + 1];
            }
            #pragma unroll
            for (int o = 16; o; o >>= 1) s += __shfl_xor_sync(0xffffffffu, s, o);
            if (lane == 0) rsm[wid] = s;
            __syncthreads();
            if (tid < 4) {
                const float v = rsm[4 * tid] + rsm[4 * tid + 1] + rsm[4 * tid + 2]
                              + rsm[4 * tid + 3] + bro[0];
                const int b = ct * 4 + tid;
                y[(size_t)b * T_STEPS + t] = v;
                g_x0[b] = v;
            }
            grid_sync(gen);
        }
    }
}

extern "C" void kernel_launch(void* const* d_in, const int* in_sizes, int n_in,
                              void* d_out, int out_size)
{
    const float* x     = (const float*)d_in[0];  // (512, 1024)
    const float* W_ih0 = (const float*)d_in[1];  // (4096, 1)
    const float* W_ihr = (const float*)d_in[2];  // (4, 4096, 1024)
    const float* W_hh  = (const float*)d_in[3];  // (5, 4096, 1024)
    const float* b_ih  = (const float*)d_in[4];  // (5, 4096)
    const float* b_hh  = (const float*)d_in[5];  // (5, 4096)
    const float* W_ro  = (const float*)d_in[6];  // (1, 1024)
    const float* b_ro  = (const float*)d_in[7];  // (1,)
    float* y = (float*)d_out;                    // (512, 128, 1)

    cudaFuncSetAttribute(lstm_persist, cudaFuncAttributeMaxDynamicSharedMemorySize, SMEM_REQ);

    wconv<<<4096, 256>>>(W_ihr, W_hh);
    lstm_init<<<(NL * BS * H + 255) / 256, 256>>>(x);
    lstm_persist<<<NCTA, NT, SMEM_REQ>>>(W_ih0, b_ih, b_hh, W_ro, b_ro, y);
}